// round 1
// baseline (speedup 1.0000x reference)
#include <cuda_runtime.h>
#include <cstdint>

// Problem: NLCCSCriterion — 128 independent 256x256 masks.
// One CTA (1024 threads) per image. Labels live in smem as uint16 (min-index
// union-find == reference's min-propagation fixed point). Areas in a 32MB
// __device__ scratch via warp-aggregated L2 atomics. Top-2 via packed keys
// replicating jax.lax.top_k tie-breaking (smaller index first).

#define HH 256
#define WW 256
#define NPIX (HH * WW)          // 65536
#define NIMG 128
#define NT 1024
#define PPT (NPIX / NT)         // 64
#define BGLAB 0x10000u          // sentinel label S = 65536

// smem layout offsets (bytes)
#define OFF_L     0             // uint16 labels[65536]            : 131072
#define OFF_FGW   131072        // uint32 fg bitmap[2048]          : 8192
#define OFF_TOP   139264        // u64 warp top2[64]               : 512
#define OFF_WSF   139776        // float warp sums[32]             : 128
#define OFF_WSI   139904        // int warp sums[32]               : 128
#define OFF_BB    140032        // int bbox[4]                     : 16
#define OFF_MISC  140048        // int misc[2]: [0]=second, [1]=fgtot
#define SMEM_BYTES 140064

__device__ int   g_area[NIMG][NPIX];   // 32 MB scratch (allowed: __device__ global)
__device__ float g_loss[NIMG];

__device__ __forceinline__ unsigned short atomicMinU16(unsigned short* addr, unsigned short val) {
    unsigned short old = *addr;
    while (old > val) {
        unsigned short prev = atomicCAS(addr, old, val);
        if (prev == old) return prev;   // we wrote; return value seen before write
        old = prev;
    }
    return old;                          // already <= val
}

__device__ __forceinline__ void merge_labels(unsigned short* L, unsigned a, unsigned b) {
    while (true) {
        unsigned short n;
        while ((n = L[a]) != (unsigned short)a) a = n;   // find root(a)
        while ((n = L[b]) != (unsigned short)b) b = n;   // find root(b)
        if (a == b) return;
        unsigned hi = a > b ? a : b;
        unsigned lo = a + b - hi;
        unsigned short old = atomicMinU16(&L[hi], (unsigned short)lo);
        if (old == (unsigned short)hi) return;           // linked hi -> lo
        a = old;                                          // keep merging displaced root
        b = lo;
    }
}

__device__ __forceinline__ void top2_merge(unsigned long long& k1, unsigned long long& k2,
                                           unsigned long long o1, unsigned long long o2) {
    if (o1 > k1) {
        k2 = (k1 > o2) ? k1 : o2;
        k1 = o1;
    } else {
        if (o1 > k2) k2 = o1;
    }
}

__global__ __launch_bounds__(NT, 1)
void nlccs_kernel(const float* __restrict__ in) {
    extern __shared__ unsigned char sraw[];
    unsigned short*      L      = (unsigned short*)(sraw + OFF_L);
    unsigned int*        fgw    = (unsigned int*)(sraw + OFF_FGW);
    unsigned long long*  s_top  = (unsigned long long*)(sraw + OFF_TOP);
    float*               s_wsf  = (float*)(sraw + OFF_WSF);
    int*                 s_wsi  = (int*)(sraw + OFF_WSI);
    int*                 s_bb   = (int*)(sraw + OFF_BB);
    int*                 s_misc = (int*)(sraw + OFF_MISC);

    const int t    = threadIdx.x;
    const int lane = t & 31;
    const int warp = t >> 5;
    const int b    = blockIdx.x;
    const float* img  = in + (size_t)b * NPIX;
    int*         area = &g_area[b][0];

    // ---------- Phase A: load, threshold, init labels + bitmap, zero areas ----------
    int fgl = 0;
    #pragma unroll 4
    for (int i = 0; i < PPT; ++i) {
        int p = t + i * NT;
        float x = __ldg(&img[p]);
        float m = fmaxf((x + 1.0f) * 0.5f, 0.0f);   // exact reference arithmetic
        bool fg = m > 0.5f;
        unsigned bal = __ballot_sync(0xFFFFFFFFu, fg);
        if (lane == 0) fgw[p >> 5] = bal;           // consecutive lanes = consecutive p
        if (fg) L[p] = (unsigned short)p;
        fgl += fg ? 1 : 0;
        __stcg(&area[p], 0);                        // L2-only, avoids stale-L1 later
    }
    for (int o = 16; o; o >>= 1) fgl += __shfl_down_sync(0xFFFFFFFFu, fgl, o);
    if (lane == 0) s_wsi[warp] = fgl;
    if (t == 0) { s_bb[0] = HH; s_bb[1] = -1; s_bb[2] = WW; s_bb[3] = -1; }
    __syncthreads();
    if (t == 0) {
        int tot = 0;
        #pragma unroll
        for (int w = 0; w < 32; ++w) tot += s_wsi[w];
        s_misc[1] = tot;                            // total fg count
    }

    // ---------- Phase B: union with prior neighbors (8-connectivity) ----------
    #pragma unroll 2
    for (int i = 0; i < PPT; ++i) {
        int p = t + i * NT;
        if (!((fgw[p >> 5] >> (p & 31)) & 1u)) continue;
        int c = p & (WW - 1);
        if (c > 0 && ((fgw[(p - 1) >> 5] >> ((p - 1) & 31)) & 1u))
            merge_labels(L, p, p - 1);
        if (p >= WW) {
            int q = p - WW;
            unsigned wbits = fgw[q >> 5];           // q..q+? share word only partially; recheck per-bit
            if ((fgw[q >> 5] >> (q & 31)) & 1u)               merge_labels(L, p, q);
            if (c > 0       && ((fgw[(q - 1) >> 5] >> ((q - 1) & 31)) & 1u)) merge_labels(L, p, q - 1);
            if (c < WW - 1  && ((fgw[(q + 1) >> 5] >> ((q + 1) & 31)) & 1u)) merge_labels(L, p, q + 1);
            (void)wbits;
        }
    }
    __syncthreads();

    // ---------- Phase C: flatten labels to roots (root == min index of component) ----------
    #pragma unroll 2
    for (int i = 0; i < PPT; ++i) {
        int p = t + i * NT;
        if (!((fgw[p >> 5] >> (p & 31)) & 1u)) continue;
        unsigned x = p;
        unsigned short n;
        while ((n = L[x]) != (unsigned short)x) x = n;
        L[p] = (unsigned short)x;
    }
    __syncthreads();

    // ---------- Phase D: per-root area histogram (warp-aggregated L2 atomics) ----------
    #pragma unroll 2
    for (int i = 0; i < PPT; ++i) {
        int p = t + i * NT;
        bool fg = (fgw[p >> 5] >> (p & 31)) & 1u;
        unsigned root = fg ? (unsigned)L[p] : BGLAB;
        unsigned mm = __match_any_sync(0xFFFFFFFFu, root);
        if (root != BGLAB && lane == (__ffs(mm) - 1))
            atomicAdd(&area[root], __popc(mm));
    }
    __threadfence();
    __syncthreads();

    // ---------- Phase E: top-2 over 65537 candidates (areas[0..65535] + background) ----------
    // key = (area << 17) | (0x1FFFF - idx): max key == largest area, smaller idx wins ties
    // — exactly jax.lax.top_k ordering.
    unsigned long long k1 = 0, k2 = 0;
    #pragma unroll 4
    for (int i = 0; i < PPT; ++i) {
        int idx = t + i * NT;
        unsigned a = (unsigned)__ldcg(&area[idx]);
        unsigned long long k = ((unsigned long long)a << 17) | (unsigned)(0x1FFFFu - idx);
        if (k > k1) { k2 = k1; k1 = k; } else if (k > k2) k2 = k;
    }
    if (t == 0) {
        unsigned bg = (unsigned)(NPIX - s_misc[1]);
        unsigned long long k = ((unsigned long long)bg << 17) | (0x1FFFFu - BGLAB); // low = 0xFFFF
        if (k > k1) { k2 = k1; k1 = k; } else if (k > k2) k2 = k;
    }
    for (int o = 16; o; o >>= 1) {
        unsigned long long o1 = __shfl_down_sync(0xFFFFFFFFu, k1, o);
        unsigned long long o2 = __shfl_down_sync(0xFFFFFFFFu, k2, o);
        top2_merge(k1, k2, o1, o2);
    }
    if (lane == 0) { s_top[warp * 2] = k1; s_top[warp * 2 + 1] = k2; }
    __syncthreads();
    if (warp == 0) {
        k1 = s_top[lane * 2];
        k2 = s_top[lane * 2 + 1];
        for (int o = 16; o; o >>= 1) {
            unsigned long long o1 = __shfl_down_sync(0xFFFFFFFFu, k1, o);
            unsigned long long o2 = __shfl_down_sync(0xFFFFFFFFu, k2, o);
            top2_merge(k1, k2, o1, o2);
        }
        if (lane == 0)
            s_misc[0] = (int)(0x1FFFFu - (unsigned)(k2 & 0x1FFFFu));  // second-largest label
    }
    __syncthreads();
    const int second = s_misc[0];

    // ---------- Phase F: bounding box of `lab == second` ----------
    {
        int mnr = HH, mxr = -1, mnc = WW, mxc = -1;
        #pragma unroll 2
        for (int i = 0; i < PPT; ++i) {
            int p = t + i * NT;
            bool fg = (fgw[p >> 5] >> (p & 31)) & 1u;
            int lab = fg ? (int)L[p] : (int)BGLAB;
            if (lab == second) {
                int r = p >> 8, c = p & (WW - 1);
                mnr = min(mnr, r); mxr = max(mxr, r);
                mnc = min(mnc, c); mxc = max(mxc, c);
            }
        }
        if (mxr >= 0) {
            atomicMin(&s_bb[0], mnr); atomicMax(&s_bb[1], mxr);
            atomicMin(&s_bb[2], mnc); atomicMax(&s_bb[3], mxc);
        }
    }
    __syncthreads();
    const int h0 = s_bb[0], h1 = s_bb[1] + 1, w0 = s_bb[2], w1 = s_bb[3] + 1;
    // empty selection => h0=256,h1=0 => inside always false => pmask == 1 (matches ref)

    // ---------- Phase G: loss = mean(pmask * m) ----------
    float s = 0.0f;
    #pragma unroll 4
    for (int i = 0; i < PPT; ++i) {
        int p = t + i * NT;
        float x = __ldg(&img[p]);
        float m = fmaxf((x + 1.0f) * 0.5f, 0.0f);
        int r = p >> 8, c = p & (WW - 1);
        bool inside = (r >= h0) & (r < h1) & (c >= w0) & (c < w1);
        if (!inside) s += m;
    }
    for (int o = 16; o; o >>= 1) s += __shfl_down_sync(0xFFFFFFFFu, s, o);
    if (lane == 0) s_wsf[warp] = s;
    __syncthreads();
    if (t == 0) {
        float tot = 0.0f;
        #pragma unroll
        for (int w = 0; w < 32; ++w) tot += s_wsf[w];
        g_loss[b] = tot * (1.0f / (float)NPIX);
    }
}

__global__ void nlccs_reduce(float* __restrict__ out) {
    int lane = threadIdx.x;   // 32 threads
    float s = g_loss[lane] + g_loss[lane + 32] + g_loss[lane + 64] + g_loss[lane + 96];
    for (int o = 16; o; o >>= 1) s += __shfl_down_sync(0xFFFFFFFFu, s, o);
    if (lane == 0) out[0] = s * (1.0f / (float)NIMG);
}

extern "C" void kernel_launch(void* const* d_in, const int* in_sizes, int n_in,
                              void* d_out, int out_size) {
    const float* in = (const float*)d_in[0];
    float* out = (float*)d_out;
    (void)in_sizes; (void)n_in; (void)out_size;

    cudaFuncSetAttribute(nlccs_kernel, cudaFuncAttributeMaxDynamicSharedMemorySize, SMEM_BYTES);
    nlccs_kernel<<<NIMG, NT, SMEM_BYTES>>>(in);
    nlccs_reduce<<<1, 32>>>(out);
}

// round 3
// speedup vs baseline: 4.7232x; 4.7232x over previous
#include <cuda_runtime.h>
#include <cstdint>

// NLCCSCriterion — 128 independent 256x256 masks, one CTA per image.
// R2: run-start initial labels + Playne-pruned word-mask merges + path-halving
// union-find. Areas via warp-aggregated L2 atomics into __device__ scratch.

#define HH 256
#define WW 256
#define NPIX (HH * WW)          // 65536
#define NIMG 128
#define NT 1024
#define PPT (NPIX / NT)         // 64
#define NWORDS (NPIX / 32)      // 2048 bitmap words, 8 per row
#define BGLAB 0x10000u          // sentinel label S = 65536

// smem layout offsets (bytes)
#define OFF_L     0             // uint16 labels[65536]            : 131072
#define OFF_FGW   131072        // uint32 fg bitmap[2048]          : 8192
#define OFF_TOP   139264        // u64 warp top2[64]               : 512
#define OFF_WSF   139776        // float warp sums[32]             : 128
#define OFF_WSI   139904        // int warp sums[32]               : 128
#define OFF_BB    140032        // int bbox[4]                     : 16
#define OFF_MISC  140048        // int misc[2]: [0]=second, [1]=fgtot
#define SMEM_BYTES 140064

__device__ int   g_area[NIMG][NPIX];   // 32 MB scratch
__device__ float g_loss[NIMG];

__device__ __forceinline__ unsigned short atomicMinU16(unsigned short* addr, unsigned short val) {
    unsigned short old = *addr;
    while (old > val) {
        unsigned short prev = atomicCAS(addr, old, val);
        if (prev == old) return prev;
        old = prev;
    }
    return old;
}

// find root with path halving (lock-free safe: stores are always ancestors,
// parent values only decrease, roots are only modified via CAS in the linker)
__device__ __forceinline__ unsigned find_halve(unsigned short* L, unsigned a) {
    unsigned short n;
    while ((n = L[a]) != (unsigned short)a) {
        unsigned short nn = L[n];
        L[a] = nn;
        a = nn;
    }
    return a;
}

__device__ __forceinline__ void merge_labels(unsigned short* L, unsigned a, unsigned b) {
    while (true) {
        a = find_halve(L, a);
        b = find_halve(L, b);
        if (a == b) return;
        unsigned hi = a > b ? a : b;
        unsigned lo = a + b - hi;
        unsigned short old = atomicMinU16(&L[hi], (unsigned short)lo);
        if (old == (unsigned short)hi) return;  // linked hi -> lo
        a = old;                                 // displaced root: keep merging
        b = lo;
    }
}

__device__ __forceinline__ void top2_merge(unsigned long long& k1, unsigned long long& k2,
                                           unsigned long long o1, unsigned long long o2) {
    if (o1 > k1) { k2 = (k1 > o2) ? k1 : o2; k1 = o1; }
    else if (o1 > k2) k2 = o1;
}

__global__ __launch_bounds__(NT, 1)
void nlccs_kernel(const float* __restrict__ in) {
    extern __shared__ unsigned char sraw[];
    unsigned short*      L      = (unsigned short*)(sraw + OFF_L);
    unsigned int*        fgw    = (unsigned int*)(sraw + OFF_FGW);
    unsigned long long*  s_top  = (unsigned long long*)(sraw + OFF_TOP);
    float*               s_wsf  = (float*)(sraw + OFF_WSF);
    int*                 s_wsi  = (int*)(sraw + OFF_WSI);
    int*                 s_bb   = (int*)(sraw + OFF_BB);
    int*                 s_misc = (int*)(sraw + OFF_MISC);

    const int t    = threadIdx.x;
    const int lane = t & 31;
    const int warp = t >> 5;
    const int b    = blockIdx.x;
    const float* img  = in + (size_t)b * NPIX;
    int*         area = &g_area[b][0];

    // ---------- Phase A: load/threshold, bitmap, RUN-START labels, zero areas ----------
    int fgl = 0;
    #pragma unroll 4
    for (int i = 0; i < PPT; ++i) {
        int p = t + i * NT;                          // bit (p&31) == lane
        float x = __ldg(&img[p]);
        float m = fmaxf((x + 1.0f) * 0.5f, 0.0f);    // exact reference arithmetic
        bool fg = m > 0.5f;
        unsigned bal = __ballot_sync(0xFFFFFFFFu, fg);
        if (lane == 0) fgw[p >> 5] = bal;
        if (fg) {
            // run start within this 32-bit word: position after nearest 0 below lane
            unsigned zb = ~bal & (lane ? ((1u << lane) - 1u) : 0u);
            unsigned rs = zb ? (32u - (unsigned)__clz(zb)) : 0u;
            L[p] = (unsigned short)((p & ~31) + rs);
        }
        fgl += fg ? 1 : 0;
        __stcg(&area[p], 0);
    }
    for (int o = 16; o; o >>= 1) fgl += __shfl_down_sync(0xFFFFFFFFu, fgl, o);
    if (lane == 0) s_wsi[warp] = fgl;
    if (t == 0) { s_bb[0] = HH; s_bb[1] = -1; s_bb[2] = WW; s_bb[3] = -1; }
    __syncthreads();
    if (t == 0) {
        int tot = 0;
        #pragma unroll
        for (int w = 0; w < 32; ++w) tot += s_wsi[w];
        s_misc[1] = tot;
    }
    __syncthreads();   // bitmap + labels visible to all

    // ---------- Phase B: pruned merges, whole-word masks ----------
    #pragma unroll
    for (int wi = 0; wi < NWORDS / NT; ++wi) {
        const int w = t + wi * NT;
        const unsigned cur = fgw[w];
        if (!cur) continue;
        const int wc  = w & 7;          // word-in-row
        const int row = w >> 3;
        const unsigned base = (unsigned)w << 5;

        const unsigned prev31 = (wc > 0) ? (fgw[w - 1] >> 31) & 1u : 0u;
        if ((cur & 1u) && prev31)
            merge_labels(L, base, base - 1);          // horizontal word boundary

        if (row > 0) {
            const unsigned up   = fgw[w - 8];
            const unsigned upl31 = (wc > 0) ? (fgw[w - 9] >> 31) & 1u : 0u;
            const unsigned upr0  = (wc < 7) ? (fgw[w - 7] & 1u) : 0u;
            const unsigned nxt0  = (wc < 7) ? (fgw[w + 1] & 1u) : 0u;

            const unsigned westc = (cur << 1) | prev31;
            const unsigned westu = (up  << 1) | upl31;
            const unsigned eastc = (cur >> 1) | (nxt0 << 31);
            const unsigned eastu = (up  >> 1) | (upr0 << 31);

            // Playne 8-connectivity pruning:
            unsigned maskN  = cur & up    & ~(westc & westu);
            unsigned maskNW = cur & westu & ~up & ~westc;
            unsigned maskNE = cur & eastu & ~up & ~eastc;

            const unsigned baseu = base - WW;
            while (maskN)  { int j = __ffs(maskN)  - 1; maskN  &= maskN  - 1; merge_labels(L, base + j, baseu + j); }
            while (maskNW) { int j = __ffs(maskNW) - 1; maskNW &= maskNW - 1; merge_labels(L, base + j, baseu + j - 1); }
            while (maskNE) { int j = __ffs(maskNE) - 1; maskNE &= maskNE - 1; merge_labels(L, base + j, baseu + j + 1); }
        }
    }
    __syncthreads();

    // ---------- Phase C: flatten (pass1 halving, pass2 write true roots) ----------
    #pragma unroll 2
    for (int i = 0; i < PPT; ++i) {
        int p = t + i * NT;
        if ((fgw[p >> 5] >> (p & 31)) & 1u) (void)find_halve(L, p);
    }
    __syncthreads();
    #pragma unroll 2
    for (int i = 0; i < PPT; ++i) {
        int p = t + i * NT;
        if (!((fgw[p >> 5] >> (p & 31)) & 1u)) continue;
        unsigned x = p;
        unsigned short n;
        while ((n = L[x]) != (unsigned short)x) x = n;   // read-only, short after halving
        L[p] = (unsigned short)x;
    }
    __syncthreads();

    // ---------- Phase D: per-root areas (warp-aggregated L2 atomics) ----------
    #pragma unroll 2
    for (int i = 0; i < PPT; ++i) {
        int p = t + i * NT;
        bool fg = (fgw[p >> 5] >> (p & 31)) & 1u;
        unsigned root = fg ? (unsigned)L[p] : BGLAB;
        unsigned mm = __match_any_sync(0xFFFFFFFFu, root);
        if (root != BGLAB && lane == (__ffs(mm) - 1))
            atomicAdd(&area[root], __popc(mm));
    }
    __threadfence();
    __syncthreads();

    // ---------- Phase E: top-2 (key = area<<17 | (0x1FFFF-idx), JAX tie order) ----------
    unsigned long long k1 = 0, k2 = 0;
    #pragma unroll 4
    for (int i = 0; i < PPT; ++i) {
        int idx = t + i * NT;
        unsigned a = (unsigned)__ldcg(&area[idx]);
        unsigned long long k = ((unsigned long long)a << 17) | (unsigned)(0x1FFFFu - idx);
        if (k > k1) { k2 = k1; k1 = k; } else if (k > k2) k2 = k;
    }
    if (t == 0) {
        unsigned bg = (unsigned)(NPIX - s_misc[1]);
        unsigned long long k = ((unsigned long long)bg << 17) | (0x1FFFFu - BGLAB);
        if (k > k1) { k2 = k1; k1 = k; } else if (k > k2) k2 = k;
    }
    for (int o = 16; o; o >>= 1) {
        unsigned long long o1 = __shfl_down_sync(0xFFFFFFFFu, k1, o);
        unsigned long long o2 = __shfl_down_sync(0xFFFFFFFFu, k2, o);
        top2_merge(k1, k2, o1, o2);
    }
    if (lane == 0) { s_top[warp * 2] = k1; s_top[warp * 2 + 1] = k2; }
    __syncthreads();
    if (warp == 0) {
        k1 = s_top[lane * 2];
        k2 = s_top[lane * 2 + 1];
        for (int o = 16; o; o >>= 1) {
            unsigned long long o1 = __shfl_down_sync(0xFFFFFFFFu, k1, o);
            unsigned long long o2 = __shfl_down_sync(0xFFFFFFFFu, k2, o);
            top2_merge(k1, k2, o1, o2);
        }
        if (lane == 0)
            s_misc[0] = (int)(0x1FFFFu - (unsigned)(k2 & 0x1FFFFu));
    }
    __syncthreads();
    const int second = s_misc[0];

    // ---------- Phase F: bbox of (lab == second) ----------
    {
        int mnr = HH, mxr = -1, mnc = WW, mxc = -1;
        #pragma unroll 2
        for (int i = 0; i < PPT; ++i) {
            int p = t + i * NT;
            bool fg = (fgw[p >> 5] >> (p & 31)) & 1u;
            int lab = fg ? (int)L[p] : (int)BGLAB;
            if (lab == second) {
                int r = p >> 8, c = p & (WW - 1);
                mnr = min(mnr, r); mxr = max(mxr, r);
                mnc = min(mnc, c); mxc = max(mxc, c);
            }
        }
        if (mxr >= 0) {
            atomicMin(&s_bb[0], mnr); atomicMax(&s_bb[1], mxr);
            atomicMin(&s_bb[2], mnc); atomicMax(&s_bb[3], mxc);
        }
    }
    __syncthreads();
    const int h0 = s_bb[0], h1 = s_bb[1] + 1, w0 = s_bb[2], w1 = s_bb[3] + 1;

    // ---------- Phase G: loss = mean(pmask * m) ----------
    float s = 0.0f;
    #pragma unroll 4
    for (int i = 0; i < PPT; ++i) {
        int p = t + i * NT;
        float x = __ldg(&img[p]);
        float m = fmaxf((x + 1.0f) * 0.5f, 0.0f);
        int r = p >> 8, c = p & (WW - 1);
        bool inside = (r >= h0) & (r < h1) & (c >= w0) & (c < w1);
        if (!inside) s += m;
    }
    for (int o = 16; o; o >>= 1) s += __shfl_down_sync(0xFFFFFFFFu, s, o);
    if (lane == 0) s_wsf[warp] = s;
    __syncthreads();
    if (t == 0) {
        float tot = 0.0f;
        #pragma unroll
        for (int w = 0; w < 32; ++w) tot += s_wsf[w];
        g_loss[b] = tot * (1.0f / (float)NPIX);
    }
}

__global__ void nlccs_reduce(float* __restrict__ out) {
    int lane = threadIdx.x;   // 32 threads
    float s = g_loss[lane] + g_loss[lane + 32] + g_loss[lane + 64] + g_loss[lane + 96];
    for (int o = 16; o; o >>= 1) s += __shfl_down_sync(0xFFFFFFFFu, s, o);
    if (lane == 0) out[0] = s * (1.0f / (float)NIMG);
}

// no-op padding so ncu (-s 5 -c 1) lands on the MAIN kernel (launch #6)
__global__ void nlccs_nop() {}

extern "C" void kernel_launch(void* const* d_in, const int* in_sizes, int n_in,
                              void* d_out, int out_size) {
    const float* in = (const float*)d_in[0];
    float* out = (float*)d_out;
    (void)in_sizes; (void)n_in; (void)out_size;

    cudaFuncSetAttribute(nlccs_kernel, cudaFuncAttributeMaxDynamicSharedMemorySize, SMEM_BYTES);
    nlccs_kernel<<<NIMG, NT, SMEM_BYTES>>>(in);
    nlccs_reduce<<<1, 32>>>(out);
    nlccs_nop<<<1, 32>>>();
    nlccs_nop<<<1, 32>>>();
    nlccs_nop<<<1, 32>>>();
}

// round 4
// speedup vs baseline: 4.8497x; 1.0268x over previous
#include <cuda_runtime.h>
#include <cstdint>

// NLCCSCriterion — 128 independent 256x256 masks, one CTA per image.
// R3: single fused kernel (last-block reduce), sparse area touch (roots only,
// read+rezero by owner), run-start-only flatten, per-pixel roots recovered via
// L[runstart] with warp-broadcast bitmap words.

#define HH 256
#define WW 256
#define NPIX (HH * WW)          // 65536
#define NIMG 128
#define NT 1024
#define PPT (NPIX / NT)         // 64
#define NWORDS (NPIX / 32)      // 2048 bitmap words, 8 per row
#define BGLAB 0x10000u          // sentinel label S = 65536

// smem layout offsets (bytes)
#define OFF_L     0             // uint16 labels[65536]            : 131072
#define OFF_FGW   131072        // uint32 fg bitmap[2048]          : 8192
#define OFF_TOP   139264        // u64 warp top2[64]               : 512
#define OFF_WSF   139776        // float warp sums[32]             : 128
#define OFF_WSI   139904        // int warp sums[32]               : 128
#define OFF_BB    140032        // int bbox[4]                     : 16
#define OFF_MISC  140048        // int misc[2]: [0]=second/flag, [1]=fgtot
#define SMEM_BYTES 140064

__device__ int      g_area[NIMG][NPIX];   // 32 MB scratch; all-zero except roots mid-call
__device__ float    g_loss[NIMG];
__device__ unsigned g_count;              // last-block counter (net-zero per call)

__device__ __forceinline__ unsigned short atomicMinU16(unsigned short* addr, unsigned short val) {
    unsigned short old = *addr;
    while (old > val) {
        unsigned short prev = atomicCAS(addr, old, val);
        if (prev == old) return prev;
        old = prev;
    }
    return old;
}

// find root with path halving (lock-free safe: stores always write ancestors,
// parents only decrease; roots only change via CAS in the linker)
__device__ __forceinline__ unsigned find_halve(unsigned short* L, unsigned a) {
    unsigned short n;
    while ((n = L[a]) != (unsigned short)a) {
        unsigned short nn = L[n];
        L[a] = nn;
        a = nn;
    }
    return a;
}

__device__ __forceinline__ void merge_labels(unsigned short* L, unsigned a, unsigned b) {
    while (true) {
        a = find_halve(L, a);
        b = find_halve(L, b);
        if (a == b) return;
        unsigned hi = a > b ? a : b;
        unsigned lo = a + b - hi;
        unsigned short old = atomicMinU16(&L[hi], (unsigned short)lo);
        if (old == (unsigned short)hi) return;  // linked hi -> lo
        a = old;                                 // displaced root: keep merging
        b = lo;
    }
}

__device__ __forceinline__ void top2_merge(unsigned long long& k1, unsigned long long& k2,
                                           unsigned long long o1, unsigned long long o2) {
    if (o1 > k1) { k2 = (k1 > o2) ? k1 : o2; k1 = o1; }
    else if (o1 > k2) k2 = o1;
}

__global__ __launch_bounds__(NT, 1)
void nlccs_kernel(const float* __restrict__ in, float* __restrict__ out) {
    extern __shared__ unsigned char sraw[];
    unsigned short*      L      = (unsigned short*)(sraw + OFF_L);
    unsigned int*        fgw    = (unsigned int*)(sraw + OFF_FGW);
    unsigned long long*  s_top  = (unsigned long long*)(sraw + OFF_TOP);
    float*               s_wsf  = (float*)(sraw + OFF_WSF);
    int*                 s_wsi  = (int*)(sraw + OFF_WSI);
    int*                 s_bb   = (int*)(sraw + OFF_BB);
    int*                 s_misc = (int*)(sraw + OFF_MISC);

    const int t    = threadIdx.x;
    const int lane = t & 31;          // == p & 31 for p = t + i*NT
    const int warp = t >> 5;
    const int b    = blockIdx.x;
    const float* img  = in + (size_t)b * NPIX;
    int*         area = &g_area[b][0];

    // ---------- Phase A: load/threshold, bitmap, run-start labels ----------
    int fgl = 0;
    #pragma unroll 4
    for (int i = 0; i < PPT; ++i) {
        int p = t + i * NT;
        float x = __ldg(&img[p]);
        float m = fmaxf((x + 1.0f) * 0.5f, 0.0f);    // exact reference arithmetic
        bool fg = m > 0.5f;
        unsigned bal = __ballot_sync(0xFFFFFFFFu, fg);
        if (lane == 0) fgw[p >> 5] = bal;
        if (fg) {
            unsigned zb = ~bal & (lane ? ((1u << lane) - 1u) : 0u);
            unsigned rs = zb ? (32u - (unsigned)__clz(zb)) : 0u;
            L[p] = (unsigned short)((p & ~31) + rs);
        }
        fgl += fg ? 1 : 0;
    }
    for (int o = 16; o; o >>= 1) fgl += __shfl_down_sync(0xFFFFFFFFu, fgl, o);
    if (lane == 0) s_wsi[warp] = fgl;
    if (t == 0) { s_bb[0] = HH; s_bb[1] = -1; s_bb[2] = WW; s_bb[3] = -1; }
    __syncthreads();
    if (t == 0) {                      // only t==0 consumes s_misc[1] later
        int tot = 0;
        #pragma unroll
        for (int w = 0; w < 32; ++w) tot += s_wsi[w];
        s_misc[1] = tot;
    }

    // ---------- Phase B: pruned merges via whole-word masks ----------
    #pragma unroll
    for (int wi = 0; wi < NWORDS / NT; ++wi) {
        const int w = t + wi * NT;
        const unsigned cur = fgw[w];
        if (!cur) continue;
        const int wc  = w & 7;
        const int row = w >> 3;
        const unsigned base = (unsigned)w << 5;

        const unsigned prev31 = (wc > 0) ? (fgw[w - 1] >> 31) & 1u : 0u;
        if ((cur & 1u) && prev31)
            merge_labels(L, base, base - 1);          // horizontal word boundary

        if (row > 0) {
            const unsigned up    = fgw[w - 8];
            const unsigned upl31 = (wc > 0) ? (fgw[w - 9] >> 31) & 1u : 0u;
            const unsigned upr0  = (wc < 7) ? (fgw[w - 7] & 1u) : 0u;
            const unsigned nxt0  = (wc < 7) ? (fgw[w + 1] & 1u) : 0u;

            const unsigned westc = (cur << 1) | prev31;
            const unsigned westu = (up  << 1) | upl31;
            const unsigned eastc = (cur >> 1) | (nxt0 << 31);
            const unsigned eastu = (up  >> 1) | (upr0 << 31);

            unsigned maskN  = cur & up    & ~(westc & westu);
            unsigned maskNW = cur & westu & ~up & ~westc;
            unsigned maskNE = cur & eastu & ~up & ~eastc;

            const unsigned baseu = base - WW;
            while (maskN)  { int j = __ffs(maskN)  - 1; maskN  &= maskN  - 1; merge_labels(L, base + j, baseu + j); }
            while (maskNW) { int j = __ffs(maskNW) - 1; maskNW &= maskNW - 1; merge_labels(L, base + j, baseu + j - 1); }
            while (maskNE) { int j = __ffs(maskNE) - 1; maskNE &= maskNE - 1; merge_labels(L, base + j, baseu + j + 1); }
        }
    }
    __syncthreads();

    // ---------- Phase C: root-flatten RUN-START entries only ----------
    #pragma unroll
    for (int wi = 0; wi < NWORDS / NT; ++wi) {
        const int w = t + wi * NT;
        unsigned cur = fgw[w];
        unsigned rsm = cur & ~(cur << 1);             // word-run starts
        const unsigned base = (unsigned)w << 5;
        while (rsm) {
            int j = __ffs(rsm) - 1; rsm &= rsm - 1;
            unsigned a = base + j;
            unsigned r = find_halve(L, a);
            L[a] = (unsigned short)r;                 // run-start entry := true root
        }
    }
    __syncthreads();

    // ---------- Phase D: per-root areas (roots via L[runstart], warp-aggregated) ----------
    #pragma unroll 2
    for (int i = 0; i < PPT; ++i) {
        int p = t + i * NT;
        unsigned word = fgw[p >> 5];                  // warp-uniform: broadcast
        bool fg = (word >> lane) & 1u;
        unsigned zb = ~word & (lane ? ((1u << lane) - 1u) : 0u);
        unsigned rs = zb ? (32u - (unsigned)__clz(zb)) : 0u;
        unsigned root = fg ? (unsigned)L[(p & ~31) + rs] : BGLAB;
        unsigned mm = __match_any_sync(0xFFFFFFFFu, root);
        if (root != BGLAB && lane == (__ffs(mm) - 1))
            atomicAdd(&area[root], __popc(mm));
    }
    __threadfence();
    __syncthreads();

    // ---------- Phase E: top-2 over roots (+bg); read-then-rezero own entries ----------
    // key = (area << 17) | (0x1FFFF - idx): JAX top_k tie order (smaller idx first).
    unsigned long long k1 = 0, k2 = 0;
    #pragma unroll
    for (int wi = 0; wi < NWORDS / NT; ++wi) {
        const int w = t + wi * NT;
        unsigned cur = fgw[w];
        unsigned rsm = cur & ~(cur << 1);             // roots are always run starts
        const unsigned base = (unsigned)w << 5;
        while (rsm) {
            int j = __ffs(rsm) - 1; rsm &= rsm - 1;
            unsigned idx = base + j;
            if (L[idx] == (unsigned short)idx) {      // is a root
                unsigned a = (unsigned)__ldcg(&area[idx]);
                __stcg(&area[idx], 0);                // restore zero (owner-only)
                unsigned long long k = ((unsigned long long)a << 17) | (0x1FFFFu - idx);
                if (k > k1) { k2 = k1; k1 = k; } else if (k > k2) k2 = k;
            }
        }
    }
    if (t == 0) {
        unsigned bg = (unsigned)(NPIX - s_misc[1]);
        unsigned long long k = ((unsigned long long)bg << 17) | (0x1FFFFu - BGLAB);
        if (k > k1) { k2 = k1; k1 = k; } else if (k > k2) k2 = k;
    }
    for (int o = 16; o; o >>= 1) {
        unsigned long long o1 = __shfl_down_sync(0xFFFFFFFFu, k1, o);
        unsigned long long o2 = __shfl_down_sync(0xFFFFFFFFu, k2, o);
        top2_merge(k1, k2, o1, o2);
    }
    if (lane == 0) { s_top[warp * 2] = k1; s_top[warp * 2 + 1] = k2; }
    __syncthreads();
    if (warp == 0) {
        k1 = s_top[lane * 2];
        k2 = s_top[lane * 2 + 1];
        for (int o = 16; o; o >>= 1) {
            unsigned long long o1 = __shfl_down_sync(0xFFFFFFFFu, k1, o);
            unsigned long long o2 = __shfl_down_sync(0xFFFFFFFFu, k2, o);
            top2_merge(k1, k2, o1, o2);
        }
        if (lane == 0)
            s_misc[0] = (int)(0x1FFFFu - (unsigned)(k2 & 0x1FFFFu));
    }
    __syncthreads();
    const int second = s_misc[0];

    // ---------- Phase F: bbox of (lab == second) ----------
    {
        int mnr = HH, mxr = -1, mnc = WW, mxc = -1;
        #pragma unroll 2
        for (int i = 0; i < PPT; ++i) {
            int p = t + i * NT;
            unsigned word = fgw[p >> 5];
            bool fg = (word >> lane) & 1u;
            unsigned zb = ~word & (lane ? ((1u << lane) - 1u) : 0u);
            unsigned rs = zb ? (32u - (unsigned)__clz(zb)) : 0u;
            int lab = fg ? (int)L[(p & ~31) + rs] : (int)BGLAB;
            if (lab == second) {
                int r = p >> 8, c = p & (WW - 1);
                mnr = min(mnr, r); mxr = max(mxr, r);
                mnc = min(mnc, c); mxc = max(mxc, c);
            }
        }
        if (mxr >= 0) {
            atomicMin(&s_bb[0], mnr); atomicMax(&s_bb[1], mxr);
            atomicMin(&s_bb[2], mnc); atomicMax(&s_bb[3], mxc);
        }
    }
    __syncthreads();
    const int h0 = s_bb[0], h1 = s_bb[1] + 1, w0 = s_bb[2], w1 = s_bb[3] + 1;
    // empty selection => inside always false => pmask == 1 (matches ref)

    // ---------- Phase G: loss = mean(pmask * m) ----------
    float s = 0.0f;
    #pragma unroll 4
    for (int i = 0; i < PPT; ++i) {
        int p = t + i * NT;
        float x = __ldg(&img[p]);
        float m = fmaxf((x + 1.0f) * 0.5f, 0.0f);
        int r = p >> 8, c = p & (WW - 1);
        bool inside = (r >= h0) & (r < h1) & (c >= w0) & (c < w1);
        if (!inside) s += m;
    }
    for (int o = 16; o; o >>= 1) s += __shfl_down_sync(0xFFFFFFFFu, s, o);
    if (lane == 0) s_wsf[warp] = s;
    __syncthreads();
    if (t == 0) {
        float tot = 0.0f;
        #pragma unroll
        for (int w = 0; w < 32; ++w) tot += s_wsf[w];
        g_loss[b] = tot * (1.0f / (float)NPIX);
    }

    // ---------- last-block final reduction ----------
    __threadfence();                   // release g_loss[b]
    __syncthreads();
    if (t == 0) {
        unsigned done = atomicAdd(&g_count, 1u);
        s_misc[0] = (done == NIMG - 1) ? 1 : 0;
    }
    __syncthreads();
    if (s_misc[0]) {
        __threadfence();               // acquire all g_loss writes
        if (t < 32) {
            float s2 = __ldcg(&g_loss[t])      + __ldcg(&g_loss[t + 32])
                     + __ldcg(&g_loss[t + 64]) + __ldcg(&g_loss[t + 96]);
            for (int o = 16; o; o >>= 1) s2 += __shfl_down_sync(0xFFFFFFFFu, s2, o);
            if (t == 0) {
                out[0] = s2 * (1.0f / (float)NIMG);
                g_count = 0;           // net-zero for graph replay
            }
        }
    }
}

extern "C" void kernel_launch(void* const* d_in, const int* in_sizes, int n_in,
                              void* d_out, int out_size) {
    const float* in = (const float*)d_in[0];
    float* out = (float*)d_out;
    (void)in_sizes; (void)n_in; (void)out_size;

    cudaFuncSetAttribute(nlccs_kernel, cudaFuncAttributeMaxDynamicSharedMemorySize, SMEM_BYTES);
    nlccs_kernel<<<NIMG, NT, SMEM_BYTES>>>(in, out);
}